// round 1
// baseline (speedup 1.0000x reference)
#include <cuda_runtime.h>
#include <math.h>

#define NUM_H 24
#define LQ 1280
#define LK 2304

// ---------------- scratch (device globals; no allocations) ----------------
__device__ float g_q[4*24*1280*64];      // (B,H,LQ,64)
__device__ float g_k[4*24*2304*64];      // (B,H,LK,64)
__device__ float g_v[4*24*2304*64];
__device__ float g_ah[4*1024*1536];      // attention out, hidden part (B,S,D)
__device__ float g_ae[4*256*1536];       // attention out, encoder part (B,SE,D)
__device__ float g_mq[6144], g_sq[6144], g_mk[6144], g_sk[6144];

// ---------------- generic SGEMM: C = A(MxK) @ W(KxN) + bias ----------------
// BM=BN=128, BK=16, 256 threads, 8x8 microtile, double-buffered smem.
// heads_mode=1: scatter output to head layout ((b*24+h)*L + s_off + s)*64 + hd
__global__ void __launch_bounds__(256) gemm_kernel(
    const float* __restrict__ A, const float* __restrict__ W,
    const float* __restrict__ bias, float* __restrict__ out,
    int M, int K, int N,
    int heads_mode, int S_rows, int L, int s_off)
{
    __shared__ float As[2][16][132];   // transposed: As[k][m]
    __shared__ float Ws[2][16][132];   // Ws[k][n]
    const int tid = threadIdx.x;
    const int ty = tid >> 4, tx = tid & 15;
    const int row0 = blockIdx.y * 128;
    const int col0 = blockIdx.x * 128;

    const int ar0 = tid >> 2;              // A tile row (first half)
    const int ak0 = (tid & 3) * 4;         // A tile k offset (float4)
    const int wk0 = tid >> 5;              // W tile k row (first half)
    const int wn0 = (tid & 31) * 4;        // W tile n offset

    float acc[8][8];
    #pragma unroll
    for (int i = 0; i < 8; i++)
        #pragma unroll
        for (int j = 0; j < 8; j++) acc[i][j] = 0.f;

    float4 pa0, pa1, pw0, pw1;
    // prologue: tile 0
    pa0 = *(const float4*)&A[(size_t)(row0 + ar0) * K + ak0];
    pa1 = *(const float4*)&A[(size_t)(row0 + ar0 + 64) * K + ak0];
    pw0 = *(const float4*)&W[(size_t)wk0 * N + col0 + wn0];
    pw1 = *(const float4*)&W[(size_t)(wk0 + 8) * N + col0 + wn0];
    As[0][ak0+0][ar0] = pa0.x; As[0][ak0+1][ar0] = pa0.y;
    As[0][ak0+2][ar0] = pa0.z; As[0][ak0+3][ar0] = pa0.w;
    As[0][ak0+0][ar0+64] = pa1.x; As[0][ak0+1][ar0+64] = pa1.y;
    As[0][ak0+2][ar0+64] = pa1.z; As[0][ak0+3][ar0+64] = pa1.w;
    *(float4*)&Ws[0][wk0][wn0]   = pw0;
    *(float4*)&Ws[0][wk0+8][wn0] = pw1;
    __syncthreads();

    const int nT = K >> 4;
    for (int t = 0; t < nT; t++) {
        const int cur = t & 1;
        const bool has = (t + 1) < nT;
        if (has) {
            const int k0 = (t + 1) << 4;
            pa0 = *(const float4*)&A[(size_t)(row0 + ar0) * K + k0 + ak0];
            pa1 = *(const float4*)&A[(size_t)(row0 + ar0 + 64) * K + k0 + ak0];
            pw0 = *(const float4*)&W[(size_t)(k0 + wk0) * N + col0 + wn0];
            pw1 = *(const float4*)&W[(size_t)(k0 + wk0 + 8) * N + col0 + wn0];
        }
        #pragma unroll
        for (int k = 0; k < 16; k++) {
            float4 a0 = *(const float4*)&As[cur][k][ty*8];
            float4 a1 = *(const float4*)&As[cur][k][ty*8+4];
            float4 b0 = *(const float4*)&Ws[cur][k][tx*8];
            float4 b1 = *(const float4*)&Ws[cur][k][tx*8+4];
            float av[8] = {a0.x,a0.y,a0.z,a0.w,a1.x,a1.y,a1.z,a1.w};
            float bv[8] = {b0.x,b0.y,b0.z,b0.w,b1.x,b1.y,b1.z,b1.w};
            #pragma unroll
            for (int i = 0; i < 8; i++)
                #pragma unroll
                for (int j = 0; j < 8; j++)
                    acc[i][j] = fmaf(av[i], bv[j], acc[i][j]);
        }
        if (has) {
            const int nxt = cur ^ 1;
            As[nxt][ak0+0][ar0] = pa0.x; As[nxt][ak0+1][ar0] = pa0.y;
            As[nxt][ak0+2][ar0] = pa0.z; As[nxt][ak0+3][ar0] = pa0.w;
            As[nxt][ak0+0][ar0+64] = pa1.x; As[nxt][ak0+1][ar0+64] = pa1.y;
            As[nxt][ak0+2][ar0+64] = pa1.z; As[nxt][ak0+3][ar0+64] = pa1.w;
            *(float4*)&Ws[nxt][wk0][wn0]   = pw0;
            *(float4*)&Ws[nxt][wk0+8][wn0] = pw1;
        }
        __syncthreads();
    }

    float bv8[8];
    #pragma unroll
    for (int j = 0; j < 8; j++) bv8[j] = bias[col0 + tx*8 + j];

    if (!heads_mode) {
        #pragma unroll
        for (int i = 0; i < 8; i++) {
            const int m = row0 + ty*8 + i;
            float4 r0, r1;
            r0.x = acc[i][0]+bv8[0]; r0.y = acc[i][1]+bv8[1];
            r0.z = acc[i][2]+bv8[2]; r0.w = acc[i][3]+bv8[3];
            r1.x = acc[i][4]+bv8[4]; r1.y = acc[i][5]+bv8[5];
            r1.z = acc[i][6]+bv8[6]; r1.w = acc[i][7]+bv8[7];
            *(float4*)&out[(size_t)m*N + col0 + tx*8]     = r0;
            *(float4*)&out[(size_t)m*N + col0 + tx*8 + 4] = r1;
        }
    } else {
        const int colb = col0 + tx*8;
        const int h = colb >> 6, hd = colb & 63;
        #pragma unroll
        for (int i = 0; i < 8; i++) {
            const int m = row0 + ty*8 + i;
            const int b = m / S_rows;
            const int s = m - b * S_rows;
            const size_t o = ((size_t)(b*NUM_H + h) * L + s_off + s) * 64 + hd;
            float4 r0, r1;
            r0.x = acc[i][0]+bv8[0]; r0.y = acc[i][1]+bv8[1];
            r0.z = acc[i][2]+bv8[2]; r0.w = acc[i][3]+bv8[3];
            r1.x = acc[i][4]+bv8[4]; r1.y = acc[i][5]+bv8[5];
            r1.z = acc[i][6]+bv8[6]; r1.w = acc[i][7]+bv8[7];
            *(float4*)&out[o]     = r0;
            *(float4*)&out[o + 4] = r1;
        }
    }
}

// ---------------- per-(b,h,d) mean/std over s=0..1023 (ddof=1) ----------------
__global__ void stats_kernel(const float* __restrict__ buf, int L,
                             float* __restrict__ mean, float* __restrict__ stdev)
{
    const int bh = blockIdx.x;                 // 0..95
    const int tx = threadIdx.x & 63;
    const int ty = threadIdx.x >> 6;           // 0..3
    const float* p = buf + (size_t)bh * L * 64;
    float s = 0.f, ss = 0.f;
    for (int i = ty; i < 1024; i += 4) {
        float v = p[(size_t)i*64 + tx];
        s += v; ss += v*v;
    }
    __shared__ float sh1[4][64], sh2[4][64];
    sh1[ty][tx] = s; sh2[ty][tx] = ss;
    __syncthreads();
    if (ty == 0) {
        s  = sh1[0][tx]+sh1[1][tx]+sh1[2][tx]+sh1[3][tx];
        ss = sh2[0][tx]+sh2[1][tx]+sh2[2][tx]+sh2[3][tx];
        float m = s * (1.0f/1024.0f);
        float var = (ss - 1024.0f*m*m) * (1.0f/1023.0f);
        mean[bh*64+tx]  = m;
        stdev[bh*64+tx] = sqrtf(var + 1e-5f);
    }
}

// ---------------- AdaIN apply (b in {1,3}) + KV replication ----------------
// k[STYLE_IDX] after adain == raw k of src (src in {0,2} are unmasked), so the
// replicated half is a raw copy from the source batch; styled writes only
// touch odd b first halves -> no races.
__global__ void adain_apply_kernel(
    float* __restrict__ q, float* __restrict__ k, float* __restrict__ v,
    const float* __restrict__ mq, const float* __restrict__ sq,
    const float* __restrict__ mk, const float* __restrict__ sk)
{
    const int idx = blockIdx.x * 256 + threadIdx.x;
    if (idx >= 4*24*1024*16) return;
    const int c  = (idx & 15) * 4;
    const int s  = (idx >> 4) & 1023;
    const int bh = idx >> 14;
    const int b  = bh / 24;
    const int h  = bh - b*24;
    const int src = (b >= 2) ? 2 : 0;
    const int sbh = src*24 + h;

    const size_t ksrc = ((size_t)sbh*LK + s)*64 + c;
    const size_t kdst = ((size_t)bh*LK + 1024 + s)*64 + c;
    float4 kr = *(const float4*)&k[ksrc];
    float4 vr = *(const float4*)&v[ksrc];
    *(float4*)&k[kdst] = kr;
    *(float4*)&v[kdst] = vr;

    if (b & 1) {
        const int ib = bh*64 + c, is = sbh*64 + c;
        {
            float4 mb = *(const float4*)&mq[ib], sb = *(const float4*)&sq[ib];
            float4 ms = *(const float4*)&mq[is], so = *(const float4*)&sq[is];
            const size_t qi = ((size_t)bh*LQ + s)*64 + c;
            float4 x = *(const float4*)&q[qi];
            x.x = (x.x - mb.x)/sb.x*so.x + ms.x;
            x.y = (x.y - mb.y)/sb.y*so.y + ms.y;
            x.z = (x.z - mb.z)/sb.z*so.z + ms.z;
            x.w = (x.w - mb.w)/sb.w*so.w + ms.w;
            *(float4*)&q[qi] = x;
        }
        {
            float4 mb = *(const float4*)&mk[ib], sb = *(const float4*)&sk[ib];
            float4 ms = *(const float4*)&mk[is], so = *(const float4*)&sk[is];
            const size_t ki = ((size_t)bh*LK + s)*64 + c;
            float4 x = *(const float4*)&k[ki];
            x.x = (x.x - mb.x)/sb.x*so.x + ms.x;
            x.y = (x.y - mb.y)/sb.y*so.y + ms.y;
            x.z = (x.z - mb.z)/sb.z*so.z + ms.z;
            x.w = (x.w - mb.w)/sb.w*so.w + ms.w;
            *(float4*)&k[ki] = x;
        }
    }
}

// ---------------- flash attention: q-tile 128, kv-tile 64, HD=64 ----------------
#define ATTN_SMEM ((64*132 + 64*68 + 64*68 + 128*68) * 4)   // 103424 B

__global__ void __launch_bounds__(256) attn_kernel(
    const float* __restrict__ Q, const float* __restrict__ Kb,
    const float* __restrict__ Vb,
    float* __restrict__ outh, float* __restrict__ oute)
{
    extern __shared__ float smf[];
    float* QsT = smf;                 // [64][132]  (k, r)
    float* KsT = smf + 64*132;        // [64][68]   (k, c)
    float* Vs  = KsT + 64*68;         // [64][68]   (kv, d)
    float* Ss  = Vs  + 64*68;         // [128][68]  (r, kv)

    const int qt = blockIdx.x, h = blockIdx.y, b = blockIdx.z;
    const int tid = threadIdx.x, ty = tid >> 4, tx = tid & 15;
    const size_t bh = (size_t)b*24 + h;
    const float* Qg = Q  + (bh*LQ + (size_t)qt*128) * 64;
    const float* Kg = Kb + bh*LK*64;
    const float* Vg = Vb + bh*LK*64;

    for (int idx = tid; idx < 128*16; idx += 256) {
        const int r = idx >> 4, c4 = (idx & 15) * 4;
        float4 qv = *(const float4*)&Qg[(size_t)r*64 + c4];
        QsT[(c4+0)*132 + r] = qv.x; QsT[(c4+1)*132 + r] = qv.y;
        QsT[(c4+2)*132 + r] = qv.z; QsT[(c4+3)*132 + r] = qv.w;
    }

    float o[8][4], mprev[8], lsum[8];
    #pragma unroll
    for (int i = 0; i < 8; i++) {
        mprev[i] = -1e30f; lsum[i] = 0.f;
        o[i][0] = o[i][1] = o[i][2] = o[i][3] = 0.f;
    }

    for (int kt = 0; kt < 36; kt++) {
        __syncthreads();   // prev PV done (and Q stores visible on first iter)
        const float* kp = Kg + (size_t)kt*64*64;
        const float* vp = Vg + (size_t)kt*64*64;
        for (int idx = tid; idx < 64*16; idx += 256) {
            const int r = idx >> 4, c4 = (idx & 15) * 4;
            float4 kv = *(const float4*)&kp[(size_t)r*64 + c4];
            KsT[(c4+0)*68 + r] = kv.x; KsT[(c4+1)*68 + r] = kv.y;
            KsT[(c4+2)*68 + r] = kv.z; KsT[(c4+3)*68 + r] = kv.w;
            *(float4*)&Vs[r*68 + c4] = *(const float4*)&vp[(size_t)r*64 + c4];
        }
        __syncthreads();

        float s[8][4];
        #pragma unroll
        for (int i = 0; i < 8; i++) s[i][0]=s[i][1]=s[i][2]=s[i][3]=0.f;
        #pragma unroll 4
        for (int k = 0; k < 64; k++) {
            float4 q0 = *(const float4*)&QsT[k*132 + ty*8];
            float4 q1 = *(const float4*)&QsT[k*132 + ty*8 + 4];
            float4 kk = *(const float4*)&KsT[k*68 + tx*4];
            float qa[8] = {q0.x,q0.y,q0.z,q0.w,q1.x,q1.y,q1.z,q1.w};
            #pragma unroll
            for (int i = 0; i < 8; i++) {
                s[i][0] = fmaf(qa[i], kk.x, s[i][0]);
                s[i][1] = fmaf(qa[i], kk.y, s[i][1]);
                s[i][2] = fmaf(qa[i], kk.z, s[i][2]);
                s[i][3] = fmaf(qa[i], kk.w, s[i][3]);
            }
        }

        #pragma unroll
        for (int i = 0; i < 8; i++) {
            s[i][0] *= 0.125f; s[i][1] *= 0.125f;
            s[i][2] *= 0.125f; s[i][3] *= 0.125f;
            float mx = fmaxf(fmaxf(s[i][0], s[i][1]), fmaxf(s[i][2], s[i][3]));
            mx = fmaxf(mx, __shfl_xor_sync(0xffffffffu, mx, 1));
            mx = fmaxf(mx, __shfl_xor_sync(0xffffffffu, mx, 2));
            mx = fmaxf(mx, __shfl_xor_sync(0xffffffffu, mx, 4));
            mx = fmaxf(mx, __shfl_xor_sync(0xffffffffu, mx, 8));
            const float mn = fmaxf(mprev[i], mx);
            const float corr = __expf(mprev[i] - mn);
            const float p0 = __expf(s[i][0] - mn);
            const float p1 = __expf(s[i][1] - mn);
            const float p2 = __expf(s[i][2] - mn);
            const float p3 = __expf(s[i][3] - mn);
            float rs = p0 + p1 + p2 + p3;
            rs += __shfl_xor_sync(0xffffffffu, rs, 1);
            rs += __shfl_xor_sync(0xffffffffu, rs, 2);
            rs += __shfl_xor_sync(0xffffffffu, rs, 4);
            rs += __shfl_xor_sync(0xffffffffu, rs, 8);
            lsum[i] = lsum[i]*corr + rs;
            mprev[i] = mn;
            o[i][0] *= corr; o[i][1] *= corr; o[i][2] *= corr; o[i][3] *= corr;
            float4 pv; pv.x = p0; pv.y = p1; pv.z = p2; pv.w = p3;
            *(float4*)&Ss[(ty*8+i)*68 + tx*4] = pv;
        }
        __syncthreads();

        #pragma unroll 4
        for (int j4 = 0; j4 < 16; j4++) {
            float4 v0 = *(const float4*)&Vs[(j4*4+0)*68 + tx*4];
            float4 v1 = *(const float4*)&Vs[(j4*4+1)*68 + tx*4];
            float4 v2 = *(const float4*)&Vs[(j4*4+2)*68 + tx*4];
            float4 v3 = *(const float4*)&Vs[(j4*4+3)*68 + tx*4];
            #pragma unroll
            for (int i = 0; i < 8; i++) {
                float4 p = *(const float4*)&Ss[(ty*8+i)*68 + j4*4];
                o[i][0] = fmaf(p.x, v0.x, fmaf(p.y, v1.x, fmaf(p.z, v2.x, fmaf(p.w, v3.x, o[i][0]))));
                o[i][1] = fmaf(p.x, v0.y, fmaf(p.y, v1.y, fmaf(p.z, v2.y, fmaf(p.w, v3.y, o[i][1]))));
                o[i][2] = fmaf(p.x, v0.z, fmaf(p.y, v1.z, fmaf(p.z, v2.z, fmaf(p.w, v3.z, o[i][2]))));
                o[i][3] = fmaf(p.x, v0.w, fmaf(p.y, v1.w, fmaf(p.z, v2.w, fmaf(p.w, v3.w, o[i][3]))));
            }
        }
    }

    #pragma unroll
    for (int i = 0; i < 8; i++) {
        const float inv = 1.0f / lsum[i];
        const int qidx = qt*128 + ty*8 + i;
        float4 r;
        r.x = o[i][0]*inv; r.y = o[i][1]*inv; r.z = o[i][2]*inv; r.w = o[i][3]*inv;
        if (qidx < 1024)
            *(float4*)&outh[((size_t)b*1024 + qidx)*1536 + h*64 + tx*4] = r;
        else
            *(float4*)&oute[((size_t)b*256 + (qidx-1024))*1536 + h*64 + tx*4] = r;
    }
}

// ---------------- launch ----------------
extern "C" void kernel_launch(void* const* d_in, const int* in_sizes, int n_in,
                              void* d_out, int out_size)
{
    (void)in_sizes; (void)n_in; (void)out_size;
    const float* hs  = (const float*)d_in[0];
    const float* ehs = (const float*)d_in[1];
    const float* wq  = (const float*)d_in[2];  const float* bq  = (const float*)d_in[3];
    const float* wk  = (const float*)d_in[4];  const float* bk  = (const float*)d_in[5];
    const float* wv  = (const float*)d_in[6];  const float* bv  = (const float*)d_in[7];
    const float* awq = (const float*)d_in[8];  const float* abq = (const float*)d_in[9];
    const float* awk = (const float*)d_in[10]; const float* abk = (const float*)d_in[11];
    const float* awv = (const float*)d_in[12]; const float* abv = (const float*)d_in[13];
    const float* wo  = (const float*)d_in[14]; const float* bo  = (const float*)d_in[15];
    const float* wao = (const float*)d_in[16]; const float* bao = (const float*)d_in[17];
    float* out = (float*)d_out;

    float *q, *k, *v, *ah, *ae, *mq, *sq, *mk, *sk;
    cudaGetSymbolAddress((void**)&q,  g_q);
    cudaGetSymbolAddress((void**)&k,  g_k);
    cudaGetSymbolAddress((void**)&v,  g_v);
    cudaGetSymbolAddress((void**)&ah, g_ah);
    cudaGetSymbolAddress((void**)&ae, g_ae);
    cudaGetSymbolAddress((void**)&mq, g_mq);
    cudaGetSymbolAddress((void**)&sq, g_sq);
    cudaGetSymbolAddress((void**)&mk, g_mk);
    cudaGetSymbolAddress((void**)&sk, g_sk);

    const dim3 blk(256);
    const dim3 g1(12, 32);   // N/128 x M/128 for M=4096
    const dim3 g2(12, 8);    // M=1024

    // hidden QKV -> head layout
    gemm_kernel<<<g1, blk>>>(hs, wq, bq, q, 4096, 1536, 1536, 1, 1024, LQ, 0);
    gemm_kernel<<<g1, blk>>>(hs, wk, bk, k, 4096, 1536, 1536, 1, 1024, LK, 0);
    gemm_kernel<<<g1, blk>>>(hs, wv, bv, v, 4096, 1536, 1536, 1, 1024, LK, 0);
    // encoder QKV -> concat offsets
    gemm_kernel<<<g2, blk>>>(ehs, awq, abq, q, 1024, 1536, 1536, 1, 256, LQ, 1024);
    gemm_kernel<<<g2, blk>>>(ehs, awk, abk, k, 1024, 1536, 1536, 1, 256, LK, 2048);
    gemm_kernel<<<g2, blk>>>(ehs, awv, abv, v, 1024, 1536, 1536, 1, 256, LK, 2048);
    // AdaIN stats + apply + KV replication
    stats_kernel<<<96, 256>>>(q, LQ, mq, sq);
    stats_kernel<<<96, 256>>>(k, LK, mk, sk);
    adain_apply_kernel<<<6144, 256>>>(q, k, v, mq, sq, mk, sk);
    // attention
    cudaFuncSetAttribute(attn_kernel, cudaFuncAttributeMaxDynamicSharedMemorySize, ATTN_SMEM);
    attn_kernel<<<dim3(10, 24, 4), blk, ATTN_SMEM>>>(q, k, v, ah, ae);
    // output projections
    gemm_kernel<<<g1, blk>>>(ah, wo,  bo,  out,                      4096, 1536, 1536, 0, 0, 0, 0);
    gemm_kernel<<<g2, blk>>>(ae, wao, bao, out + (size_t)4096*1536,  1024, 1536, 1536, 0, 0, 0, 0);
}